// round 4
// baseline (speedup 1.0000x reference)
#include <cuda_runtime.h>
#include <cuda_bf16.h>
#include <cstddef>

// Problem constants
#define B 128
#define T 2048
#define H 200
#define H4 800

// Scratch (device globals: no allocations allowed)
__device__ float g_qp[B * H];        // q@Wa^T + ba + bua  (bua folded in)
__device__ float g_hpre[B * H4];     // q@W_hh^T + b_hh
__device__ float g_scores[B * T];
__device__ float g_ctx[B * H];

__device__ __forceinline__ float tanh_fast(float x) {
    // accurate ~1e-6 rel; robust at +/-inf
    float p = __expf(2.0f * x);
    return 1.0f - __fdividef(2.0f, p + 1.0f);
}
__device__ __forceinline__ float sig_fast(float x) {
    return __fdividef(1.0f, 1.0f + __expf(-x));
}

// ---------------------------------------------------------------------------
// K1: q_proj[b,h] = q@Wa^T + ba + bua ;  h_pre[b,j] = q@W_hh^T + b_hh
// grid(B), block(256)
// ---------------------------------------------------------------------------
__global__ __launch_bounds__(256) void k_qproj(
    const float* __restrict__ h0, const float* __restrict__ Wa,
    const float* __restrict__ ba, const float* __restrict__ bua,
    const float* __restrict__ Whh, const float* __restrict__ bhh)
{
    int b = blockIdx.x, tid = threadIdx.x;
    __shared__ float qs[H];
    if (tid < H) qs[tid] = h0[b * H + tid];
    __syncthreads();

    if (tid < H) {
        const float* w = Wa + tid * H;
        float a0 = 0.f, a1 = 0.f, a2 = 0.f, a3 = 0.f;
        #pragma unroll 4
        for (int k = 0; k < H; k += 4) {
            a0 += w[k] * qs[k];     a1 += w[k+1] * qs[k+1];
            a2 += w[k+2] * qs[k+2]; a3 += w[k+3] * qs[k+3];
        }
        g_qp[b * H + tid] = a0 + a1 + a2 + a3 + ba[tid] + bua[tid];
    }
    for (int j = tid; j < H4; j += 256) {
        const float* w = Whh + j * H;
        float a0 = 0.f, a1 = 0.f, a2 = 0.f, a3 = 0.f;
        #pragma unroll 4
        for (int k = 0; k < H; k += 4) {
            a0 += w[k] * qs[k];     a1 += w[k+1] * qs[k+1];
            a2 += w[k+2] * qs[k+2]; a3 += w[k+3] * qs[k+3];
        }
        g_hpre[b * H4 + j] = a0 + a1 + a2 + a3 + bhh[j];
    }
}

// ---------------------------------------------------------------------------
// K2: fused scores:  scores[b,t] = bva + sum_h Va[h]*tanh(qp[b,h] + enc[b,t,:]@Ua[h,:])
// Tiled GEMM: BM=64 t-rows, BN=208 (padded from 200), BK=8. 256 threads.
// Thread tile 4x13 (rm = tid>>4 -> rows rm*4..+3, cn = tid&15 -> cols cn+16*i).
// grid(32, 128): x = t-tile, y = b
// ---------------------------------------------------------------------------
__global__ __launch_bounds__(256) void k_scores(
    const float* __restrict__ enc, const float* __restrict__ Ua,
    const float* __restrict__ Va, const float* __restrict__ bva)
{
    __shared__ float As[8][64];
    __shared__ float Bs[8][208];
    __shared__ float Vas[208], qps[208];
    __shared__ float sred[64][17];

    int b = blockIdx.y;
    int t0 = blockIdx.x * 64;
    int tid = threadIdx.x;
    int cn = tid & 15, rm = tid >> 4;

    if (tid < 208) {
        Vas[tid] = (tid < H) ? Va[tid] : 0.f;
        qps[tid] = (tid < H) ? g_qp[b * H + tid] : 0.f;
    }

    float acc[4][13];
    #pragma unroll
    for (int r = 0; r < 4; r++)
        #pragma unroll
        for (int i = 0; i < 13; i++) acc[r][i] = 0.f;

    const float* encb = enc + ((size_t)b * T + t0) * H;
    int am = tid >> 2;            // 0..63
    int ak = (tid & 3) * 2;       // 0,2,4,6
    int bn = tid >> 3;            // 0..31
    int bk = tid & 7;             // 0..7

    for (int kt = 0; kt < 25; ++kt) {
        int k0 = kt * 8;
        float2 av = *(const float2*)(encb + (size_t)am * H + k0 + ak);
        As[ak][am]     = av.x;
        As[ak + 1][am] = av.y;
        #pragma unroll
        for (int i = 0; i < 7; i++) {
            int n = bn + i * 32;
            if (n < 208) Bs[bk][n] = (n < H) ? Ua[n * H + k0 + bk] : 0.f;
        }
        __syncthreads();
        #pragma unroll
        for (int kk = 0; kk < 8; kk++) {
            float4 a = *(const float4*)&As[kk][rm * 4];
            float bb[13];
            #pragma unroll
            for (int i = 0; i < 13; i++) bb[i] = Bs[kk][cn + 16 * i];
            #pragma unroll
            for (int i = 0; i < 13; i++) {
                acc[0][i] += a.x * bb[i];
                acc[1][i] += a.y * bb[i];
                acc[2][i] += a.z * bb[i];
                acc[3][i] += a.w * bb[i];
            }
        }
        __syncthreads();
    }

    // Epilogue: tanh + Va-dot, deterministic tree reduction over 16 col-threads.
    #pragma unroll
    for (int r = 0; r < 4; r++) {
        float p = 0.f;
        #pragma unroll
        for (int i = 0; i < 13; i++) {
            int c = cn + 16 * i;
            p += Vas[c] * tanh_fast(qps[c] + acc[r][i]);
        }
        sred[rm * 4 + r][cn] = p;
    }
    __syncthreads();
    if (tid < 64) {
        float s = bva[0];
        #pragma unroll
        for (int i = 0; i < 16; i++) s += sred[tid][i];
        g_scores[(size_t)b * T + t0 + tid] = s;
    }
}

// ---------------------------------------------------------------------------
// K3: softmax over T, then context[b,h] = sum_t attn[b,t]*enc[b,t,h]
// grid(B), block(256)
// ---------------------------------------------------------------------------
__global__ __launch_bounds__(256) void k_softmax_ctx(const float* __restrict__ enc)
{
    int b = blockIdx.x, tid = threadIdx.x;
    __shared__ float sc[T];
    __shared__ float red[256];

    float m = -1e30f;
    for (int t = tid; t < T; t += 256) {
        float v = g_scores[(size_t)b * T + t];
        sc[t] = v;
        m = fmaxf(m, v);
    }
    red[tid] = m;
    __syncthreads();
    for (int s = 128; s > 0; s >>= 1) {
        if (tid < s) red[tid] = fmaxf(red[tid], red[tid + s]);
        __syncthreads();
    }
    float mx = red[0];
    __syncthreads();

    float sum = 0.f;
    for (int t = tid; t < T; t += 256) {
        float e = __expf(sc[t] - mx);
        sc[t] = e;
        sum += e;
    }
    red[tid] = sum;
    __syncthreads();
    for (int s = 128; s > 0; s >>= 1) {
        if (tid < s) red[tid] += red[tid + s];
        __syncthreads();
    }
    float total = red[0];
    __syncthreads();

    if (tid < H) {
        const float* e = enc + (size_t)b * T * H + tid;
        float a0 = 0.f, a1 = 0.f, a2 = 0.f, a3 = 0.f;
        #pragma unroll 2
        for (int t = 0; t < T; t += 4) {
            a0 += sc[t]     * e[(size_t)t * H];
            a1 += sc[t + 1] * e[(size_t)(t + 1) * H];
            a2 += sc[t + 2] * e[(size_t)(t + 2) * H];
            a3 += sc[t + 3] * e[(size_t)(t + 3) * H];
        }
        g_ctx[b * H + tid] = (a0 + a1 + a2 + a3) * (1.0f / total);
    }
}

// ---------------------------------------------------------------------------
// K4: base = W_ih[:,1:]@context + b_ih + h_pre; then 5 scalar-feedback steps.
// grid(B), block(256)
// ---------------------------------------------------------------------------
__global__ __launch_bounds__(256) void k_decoder(
    const float* __restrict__ x_in, const float* __restrict__ c0,
    const float* __restrict__ Wih, const float* __restrict__ bih,
    const float* __restrict__ W1, const float* __restrict__ b1,
    const float* __restrict__ W2, const float* __restrict__ b2,
    const float* __restrict__ W3, const float* __restrict__ b3,
    float* __restrict__ out)
{
    int b = blockIdx.x, tid = threadIdx.x;
    __shared__ float ctx[H], c0s[H], basej[H4], wx0[H4];
    __shared__ float hbuf[H], o1[100], o2[50];
    __shared__ float xs;

    if (tid < H) {
        ctx[tid] = g_ctx[b * H + tid];
        c0s[tid] = c0[b * H + tid];
    }
    __syncthreads();

    for (int j = tid; j < H4; j += 256) {
        const float* w = Wih + (size_t)j * 201;  // IN + H = 201
        wx0[j] = w[0];
        const float* wc = w + 1;
        float a0 = 0.f, a1 = 0.f, a2 = 0.f, a3 = 0.f;
        #pragma unroll 4
        for (int k = 0; k < H; k += 4) {
            a0 += wc[k] * ctx[k];     a1 += wc[k+1] * ctx[k+1];
            a2 += wc[k+2] * ctx[k+2]; a3 += wc[k+3] * ctx[k+3];
        }
        basej[j] = a0 + a1 + a2 + a3 + bih[j] + g_hpre[b * H4 + j];
    }
    if (tid == 0) xs = x_in[b];
    __syncthreads();

    for (int s = 0; s < 5; s++) {
        float xv = xs;
        __syncthreads();   // everyone has read xs before tid0 overwrites later
        if (tid < H) {
            float ig = basej[tid]       + wx0[tid]       * xv;
            float fg = basej[200 + tid] + wx0[200 + tid] * xv;
            float gg = basej[400 + tid] + wx0[400 + tid] * xv;
            float og = basej[600 + tid] + wx0[600 + tid] * xv;
            float cn = sig_fast(fg) * c0s[tid] + sig_fast(ig) * tanh_fast(gg);
            float hn = sig_fast(og) * tanh_fast(cn);
            hbuf[tid] = fmaxf(hn, 0.f);
        }
        __syncthreads();
        if (tid < 100) {
            const float* w = W1 + tid * H;
            float a = b1[tid];
            #pragma unroll 4
            for (int k = 0; k < H; k++) a += w[k] * hbuf[k];
            o1[tid] = fmaxf(a, 0.f);
        }
        __syncthreads();
        if (tid < 50) {
            const float* w = W2 + tid * 100;
            float a = b2[tid];
            #pragma unroll 4
            for (int k = 0; k < 100; k++) a += w[k] * o1[k];
            o2[tid] = fmaxf(a, 0.f);
        }
        __syncthreads();
        if (tid == 0) {
            float a = b3[0];
            #pragma unroll
            for (int k = 0; k < 50; k++) a += W3[k] * o2[k];
            out[b * 5 + s] = a;
            xs = a;
        }
        __syncthreads();
    }
}

// ---------------------------------------------------------------------------
extern "C" void kernel_launch(void* const* d_in, const int* in_sizes, int n_in,
                              void* d_out, int out_size)
{
    const float* x    = (const float*)d_in[0];   // (B,1,1)
    const float* h0   = (const float*)d_in[1];   // (1,B,H)
    const float* c0   = (const float*)d_in[2];   // (1,B,H)
    const float* enc  = (const float*)d_in[3];   // (B,T,H)
    const float* Wa   = (const float*)d_in[4];
    const float* ba   = (const float*)d_in[5];
    const float* Ua   = (const float*)d_in[6];
    const float* bua  = (const float*)d_in[7];
    const float* Va   = (const float*)d_in[8];
    const float* bva  = (const float*)d_in[9];
    const float* Wih  = (const float*)d_in[10];  // (4H, 201)
    const float* Whh  = (const float*)d_in[11];  // (4H, H)
    const float* bih  = (const float*)d_in[12];
    const float* bhh  = (const float*)d_in[13];
    const float* W1   = (const float*)d_in[14];
    const float* b1   = (const float*)d_in[15];
    const float* W2   = (const float*)d_in[16];
    const float* b2   = (const float*)d_in[17];
    const float* W3   = (const float*)d_in[18];
    const float* b3   = (const float*)d_in[19];
    float* out = (float*)d_out;

    k_qproj<<<B, 256>>>(h0, Wa, ba, bua, Whh, bhh);
    dim3 g2(T / 64, B);
    k_scores<<<g2, 256>>>(enc, Ua, Va, bva);
    k_softmax_ctx<<<B, 256>>>(enc);
    k_decoder<<<B, 256>>>(x, c0, Wih, bih, W1, b1, W2, b2, W3, b3, out);
}

// round 8
// speedup vs baseline: 1.8502x; 1.8502x over previous
#include <cuda_runtime.h>
#include <cuda_bf16.h>
#include <cstdint>
#include <cstddef>

#define B 128
#define T 2048
#define H 200
#define H4 800

// ---------------- device scratch ----------------
__device__ float g_qp[B * H];
__device__ float g_hpre[B * H4];
__device__ float g_scores[B * T];
__device__ float g_ctx[B * H];
__device__ float g_base[B * H4];
__device__ float g_wx0[H4];
// Pre-packed Ua in mma B-fragment layout: [chunk][kpair 0..31][n 0..215] b16x2
__device__ uint32_t g_Bpk_h[4 * 32 * 216];
__device__ uint32_t g_Bpk_l[4 * 32 * 216];

__device__ __forceinline__ float tanh_fast(float x) {
    float p = __expf(2.0f * x);
    return 1.0f - __fdividef(2.0f, p + 1.0f);
}
__device__ __forceinline__ float sig_fast(float x) {
    return __fdividef(1.0f, 1.0f + __expf(-x));
}
__device__ __forceinline__ uint32_t pack_bf2(__nv_bfloat16 a, __nv_bfloat16 b) {
    return (uint32_t)__bfloat16_as_ushort(a) | ((uint32_t)__bfloat16_as_ushort(b) << 16);
}
__device__ __forceinline__ void split_bf(float v, __nv_bfloat16& h, __nv_bfloat16& l) {
    h = __float2bfloat16(v);
    l = __float2bfloat16(v - __bfloat162float(h));
}
__device__ __forceinline__ void mma_bf16(float* c, const uint32_t* a, uint32_t b0, uint32_t b1) {
    asm volatile(
        "mma.sync.aligned.m16n8k16.row.col.f32.bf16.bf16.f32 "
        "{%0,%1,%2,%3}, {%4,%5,%6,%7}, {%8,%9}, {%0,%1,%2,%3};"
        : "+f"(c[0]), "+f"(c[1]), "+f"(c[2]), "+f"(c[3])
        : "r"(a[0]), "r"(a[1]), "r"(a[2]), "r"(a[3]), "r"(b0), "r"(b1));
}

// ---------------------------------------------------------------------------
// K0: pre-pack Ua into bf16 hi/lo mma-B layout. grid(4), 256 threads.
// B[k][n] pair (2p, 2p+1) at [chunk][p][n]; zero-padded n>=200 / k>=200.
// ---------------------------------------------------------------------------
__global__ __launch_bounds__(256) void k_prep(const float* __restrict__ Ua)
{
    int chunk = blockIdx.x, tid = threadIdx.x;
    for (int e = tid; e < 32 * 216; e += 256) {
        int p = e / 216, n = e % 216;
        int k = chunk * 64 + 2 * p;
        float v0 = 0.f, v1 = 0.f;
        if (n < H) {
            if (k < H)     v0 = Ua[(size_t)n * H + k];
            if (k + 1 < H) v1 = Ua[(size_t)n * H + k + 1];
        }
        __nv_bfloat16 h0, l0, h1, l1;
        split_bf(v0, h0, l0);
        split_bf(v1, h1, l1);
        g_Bpk_h[(chunk * 32 + p) * 216 + n] = pack_bf2(h0, h1);
        g_Bpk_l[(chunk * 32 + p) * 216 + n] = pack_bf2(l0, l1);
    }
}

// ---------------------------------------------------------------------------
// K1: q_proj + h_pre
// ---------------------------------------------------------------------------
__global__ __launch_bounds__(256) void k_qproj(
    const float* __restrict__ h0, const float* __restrict__ Wa,
    const float* __restrict__ ba, const float* __restrict__ bua,
    const float* __restrict__ Whh, const float* __restrict__ bhh)
{
    int b = blockIdx.x, tid = threadIdx.x;
    __shared__ float qs[H];
    if (tid < H) qs[tid] = h0[b * H + tid];
    __syncthreads();

    if (tid < H) {
        const float* w = Wa + tid * H;
        float a0 = 0.f, a1 = 0.f, a2 = 0.f, a3 = 0.f;
        #pragma unroll 4
        for (int k = 0; k < H; k += 4) {
            a0 += w[k] * qs[k];     a1 += w[k+1] * qs[k+1];
            a2 += w[k+2] * qs[k+2]; a3 += w[k+3] * qs[k+3];
        }
        g_qp[b * H + tid] = a0 + a1 + a2 + a3 + ba[tid] + bua[tid];
    }
    for (int j = tid; j < H4; j += 256) {
        const float* w = Whh + j * H;
        float a0 = 0.f, a1 = 0.f, a2 = 0.f, a3 = 0.f;
        #pragma unroll 4
        for (int k = 0; k < H; k += 4) {
            a0 += w[k] * qs[k];     a1 += w[k+1] * qs[k+1];
            a2 += w[k+2] * qs[k+2]; a3 += w[k+3] * qs[k+3];
        }
        g_hpre[b * H4 + j] = a0 + a1 + a2 + a3 + bhh[j];
    }
}

// ---------------------------------------------------------------------------
// K2: scores via mma.sync bf16 split-precision.
// Tile M=128 (t-rows) x N=208, K=208 (padded), K chunks of 64.
// 512 threads = 16 warps: widM = wid>>1 (16-row band), widN = wid&1 (104 cols).
// D += Ah*Bh + Al*Bh + Ah*Bl. Epilogue: tanh + Va-dot fused.
// grid(16, 128)
// ---------------------------------------------------------------------------
#define MTILE 128
#define NTILE 208
#define NTPAD 216
#define KC 64
// smem byte offsets
#define OFF_QPS  0            // 208 f
#define OFF_VAS  832          // 208 f
#define OFF_SRED 1664         // 128*2 f
#define OFF_AH   2944         // 128 rows * 144B
#define OFF_AL   21376
#define OFF_BH   39808        // 32 * 216 * 4
#define OFF_BL   67456
#define SMEM_SCORES 95104

__global__ __launch_bounds__(512) void k_scores(
    const float* __restrict__ enc, const float* __restrict__ Ua,
    const float* __restrict__ Va, const float* __restrict__ bva)
{
    extern __shared__ char smem[];
    const int tid = threadIdx.x;
    const int wid = tid >> 5, lane = tid & 31;
    const int widM = wid >> 1, widN = wid & 1;
    const int wm = widM * 16;
    const int b = blockIdx.y;
    const int t0 = blockIdx.x * MTILE;

    float* qps = (float*)(smem + OFF_QPS);
    float* Vas = (float*)(smem + OFF_VAS);
    float* sred = (float*)(smem + OFF_SRED);
    uint32_t* Ah32 = (uint32_t*)(smem + OFF_AH);
    uint32_t* Al32 = (uint32_t*)(smem + OFF_AL);
    const uint32_t* BH32 = (const uint32_t*)(smem + OFF_BH);
    const uint32_t* BL32 = (const uint32_t*)(smem + OFF_BL);

    if (tid < NTILE) {
        Vas[tid] = (tid < H) ? Va[tid] : 0.f;
        qps[tid] = (tid < H) ? g_qp[b * H + tid] : 0.f;
    }

    float acc[13][4];
    #pragma unroll
    for (int j = 0; j < 13; ++j)
        #pragma unroll
        for (int i = 0; i < 4; ++i) acc[j][i] = 0.f;

    const float* encb = enc + ((size_t)b * T + t0) * H;
    const int q = lane & 3, nn = lane >> 2;

    for (int c = 0; c < 4; ++c) {
        const int k0 = c * KC;
        // ---- A: 128 rows x 64 k, fp32 -> bf16 hi/lo, row stride 144B ----
        #pragma unroll
        for (int it = 0; it < 4; ++it) {
            int idx = it * 512 + tid;
            int r = idx >> 4, c4 = idx & 15;
            int kg = k0 + c4 * 4;
            float4 v = make_float4(0.f, 0.f, 0.f, 0.f);
            if (kg < H) v = *(const float4*)(encb + (size_t)r * H + kg);
            __nv_bfloat16 hx, lx, hy, ly, hz, lz, hw, lw;
            split_bf(v.x, hx, lx); split_bf(v.y, hy, ly);
            split_bf(v.z, hz, lz); split_bf(v.w, hw, lw);
            int o = r * 36 + c4 * 2;
            *(uint2*)(Ah32 + o) = make_uint2(pack_bf2(hx, hy), pack_bf2(hz, hw));
            *(uint2*)(Al32 + o) = make_uint2(pack_bf2(lx, ly), pack_bf2(lz, lw));
        }
        // ---- B: straight uint4 copy of pre-packed chunk (1728 uint4 each) ----
        {
            const uint4* gh = (const uint4*)(g_Bpk_h + c * 32 * NTPAD);
            const uint4* gl = (const uint4*)(g_Bpk_l + c * 32 * NTPAD);
            uint4* sh4 = (uint4*)(smem + OFF_BH);
            uint4* sl4 = (uint4*)(smem + OFF_BL);
            #pragma unroll
            for (int it = 0; it < 4; ++it) {
                int idx = it * 512 + tid;
                if (idx < 1728) { sh4[idx] = gh[idx]; sl4[idx] = gl[idx]; }
            }
        }
        __syncthreads();

        const int nsteps = (c < 3) ? 4 : 1;   // chunk 3: only k 192..199 valid
        for (int kk = 0; kk < nsteps; ++kk) {
            uint32_t ah[4], al[4];
            int abase = (wm + nn) * 36 + kk * 8 + q;
            ah[0] = Ah32[abase];           ah[1] = Ah32[abase + 8 * 36];
            ah[2] = Ah32[abase + 4];       ah[3] = Ah32[abase + 8 * 36 + 4];
            al[0] = Al32[abase];           al[1] = Al32[abase + 8 * 36];
            al[2] = Al32[abase + 4];       al[3] = Al32[abase + 8 * 36 + 4];
            int pb0 = (kk * 8 + q) * NTPAD + widN * 104 + nn;
            #pragma unroll
            for (int j = 0; j < 13; ++j) {
                int pb = pb0 + j * 8;
                uint32_t b0h = BH32[pb], b1h = BH32[pb + 4 * NTPAD];
                uint32_t b0l = BL32[pb], b1l = BL32[pb + 4 * NTPAD];
                mma_bf16(acc[j], ah, b0h, b1h);
                mma_bf16(acc[j], al, b0h, b1h);
                mma_bf16(acc[j], ah, b0l, b1l);
            }
        }
        __syncthreads();
    }

    // ---- epilogue: tanh + Va weighted sum, quad shuffle-reduce ----
    float p0 = 0.f, p1 = 0.f;
    #pragma unroll
    for (int j = 0; j < 13; ++j) {
        int n0 = widN * 104 + j * 8 + q * 2;
        float va0 = Vas[n0], va1 = Vas[n0 + 1];
        float q0 = qps[n0], q1 = qps[n0 + 1];
        p0 += va0 * tanh_fast(q0 + acc[j][0]) + va1 * tanh_fast(q1 + acc[j][1]);
        p1 += va0 * tanh_fast(q0 + acc[j][2]) + va1 * tanh_fast(q1 + acc[j][3]);
    }
    p0 += __shfl_xor_sync(0xffffffffu, p0, 1);
    p0 += __shfl_xor_sync(0xffffffffu, p0, 2);
    p1 += __shfl_xor_sync(0xffffffffu, p1, 1);
    p1 += __shfl_xor_sync(0xffffffffu, p1, 2);
    if (q == 0) {
        int r0 = wm + nn;
        sred[r0 * 2 + widN] = p0;
        sred[(r0 + 8) * 2 + widN] = p1;
    }
    __syncthreads();
    if (tid < MTILE)
        g_scores[(size_t)b * T + t0 + tid] = bva[0] + sred[tid * 2] + sred[tid * 2 + 1];
}

// ---------------------------------------------------------------------------
// K3: softmax + context. 1024 threads; ctx split 4-way over T.
// ---------------------------------------------------------------------------
__global__ __launch_bounds__(1024) void k_softmax_ctx(const float* __restrict__ enc)
{
    int b = blockIdx.x, tid = threadIdx.x;
    __shared__ float sc[T];
    __shared__ float red[1024];
    __shared__ float part[4][H];

    float m = -1e30f;
    for (int t = tid; t < T; t += 1024) {
        float v = g_scores[(size_t)b * T + t];
        sc[t] = v;
        m = fmaxf(m, v);
    }
    red[tid] = m;
    __syncthreads();
    for (int s = 512; s > 0; s >>= 1) {
        if (tid < s) red[tid] = fmaxf(red[tid], red[tid + s]);
        __syncthreads();
    }
    float mx = red[0];
    __syncthreads();

    float sum = 0.f;
    for (int t = tid; t < T; t += 1024) {
        float e = __expf(sc[t] - mx);
        sc[t] = e;
        sum += e;
    }
    red[tid] = sum;
    __syncthreads();
    for (int s = 512; s > 0; s >>= 1) {
        if (tid < s) red[tid] += red[tid + s];
        __syncthreads();
    }
    float total = red[0];
    __syncthreads();

    int grp = tid >> 8, h = tid & 255;
    if (h < H) {
        const float* e = enc + (size_t)b * T * H + (size_t)grp * 512 * H + h;
        const float* w = &sc[grp * 512];
        float a0 = 0.f, a1 = 0.f, a2 = 0.f, a3 = 0.f;
        #pragma unroll 2
        for (int t = 0; t < 512; t += 4) {
            a0 += w[t]     * e[(size_t)t * H];
            a1 += w[t + 1] * e[(size_t)(t + 1) * H];
            a2 += w[t + 2] * e[(size_t)(t + 2) * H];
            a3 += w[t + 3] * e[(size_t)(t + 3) * H];
        }
        part[grp][h] = a0 + a1 + a2 + a3;
    }
    __syncthreads();
    if (tid < H)
        g_ctx[b * H + tid] = (part[0][tid] + part[1][tid] + part[2][tid] + part[3][tid])
                             * (1.0f / total);
}

// ---------------------------------------------------------------------------
// K4a: base gates.  grid(4, B), 256 threads
// ---------------------------------------------------------------------------
__global__ __launch_bounds__(256) void k_base(
    const float* __restrict__ Wih, const float* __restrict__ bih)
{
    int b = blockIdx.y, tid = threadIdx.x;
    __shared__ float ctx[H];
    if (tid < H) ctx[tid] = g_ctx[b * H + tid];
    __syncthreads();
    if (tid < H) {
        int j = blockIdx.x * H + tid;
        const float* w = Wih + (size_t)j * 201;
        const float* wc = w + 1;
        float a0 = 0.f, a1 = 0.f, a2 = 0.f, a3 = 0.f;
        #pragma unroll 4
        for (int k = 0; k < H; k += 4) {
            a0 += wc[k] * ctx[k];     a1 += wc[k+1] * ctx[k+1];
            a2 += wc[k+2] * ctx[k+2]; a3 += wc[k+3] * ctx[k+3];
        }
        g_base[b * H4 + j] = a0 + a1 + a2 + a3 + bih[j] + g_hpre[b * H4 + j];
        if (b == 0) g_wx0[j] = w[0];
    }
}

// ---------------------------------------------------------------------------
// K4b: 5-step scalar-feedback decoder. grid(B), 256 threads.
// ---------------------------------------------------------------------------
__global__ __launch_bounds__(256) void k_steps(
    const float* __restrict__ x_in, const float* __restrict__ c0,
    const float* __restrict__ W1, const float* __restrict__ b1,
    const float* __restrict__ W2, const float* __restrict__ b2,
    const float* __restrict__ W3, const float* __restrict__ b3,
    float* __restrict__ out)
{
    int b = blockIdx.x, tid = threadIdx.x;
    __shared__ float bs[H4], ws[H4], c0s[H], hbuf[H], o1[100], o2[50];
    __shared__ float xs;

    for (int i = tid; i < H4; i += 256) {
        bs[i] = g_base[b * H4 + i];
        ws[i] = g_wx0[i];
    }
    if (tid < H) c0s[tid] = c0[b * H + tid];
    if (tid == 0) xs = x_in[b];
    __syncthreads();

    for (int s = 0; s < 5; ++s) {
        float xv = xs;
        if (tid < H) {
            float ig = bs[tid]       + ws[tid]       * xv;
            float fg = bs[200 + tid] + ws[200 + tid] * xv;
            float gg = bs[400 + tid] + ws[400 + tid] * xv;
            float og = bs[600 + tid] + ws[600 + tid] * xv;
            float cn = sig_fast(fg) * c0s[tid] + sig_fast(ig) * tanh_fast(gg);
            float hn = sig_fast(og) * tanh_fast(cn);
            hbuf[tid] = fmaxf(hn, 0.f);
        }
        __syncthreads();
        if (tid < 100) {
            const float* w = W1 + tid * H;
            float a0 = 0.f, a1 = 0.f, a2 = 0.f, a3 = 0.f;
            #pragma unroll 4
            for (int k = 0; k < H; k += 4) {
                a0 += w[k] * hbuf[k];     a1 += w[k+1] * hbuf[k+1];
                a2 += w[k+2] * hbuf[k+2]; a3 += w[k+3] * hbuf[k+3];
            }
            o1[tid] = fmaxf(a0 + a1 + a2 + a3 + b1[tid], 0.f);
        }
        __syncthreads();
        if (tid < 50) {
            const float* w = W2 + tid * 100;
            float a0 = 0.f, a1 = 0.f, a2 = 0.f, a3 = 0.f;
            #pragma unroll 4
            for (int k = 0; k < 100; k += 4) {
                a0 += w[k] * o1[k];     a1 += w[k+1] * o1[k+1];
                a2 += w[k+2] * o1[k+2]; a3 += w[k+3] * o1[k+3];
            }
            o2[tid] = fmaxf(a0 + a1 + a2 + a3 + b2[tid], 0.f);
        }
        __syncthreads();
        if (tid < 32) {
            float a = (tid < 50) ? W3[tid] * o2[tid] : 0.f;
            if (tid + 32 < 50) a += W3[tid + 32] * o2[tid + 32];
            #pragma unroll
            for (int sh = 16; sh > 0; sh >>= 1)
                a += __shfl_down_sync(0xffffffffu, a, sh);
            if (tid == 0) {
                float y = a + b3[0];
                out[b * 5 + s] = y;
                xs = y;
            }
        }
        __syncthreads();
    }
}

// ---------------------------------------------------------------------------
extern "C" void kernel_launch(void* const* d_in, const int* in_sizes, int n_in,
                              void* d_out, int out_size)
{
    const float* x    = (const float*)d_in[0];
    const float* h0   = (const float*)d_in[1];
    const float* c0   = (const float*)d_in[2];
    const float* enc  = (const float*)d_in[3];
    const float* Wa   = (const float*)d_in[4];
    const float* ba   = (const float*)d_in[5];
    const float* Ua   = (const float*)d_in[6];
    const float* bua  = (const float*)d_in[7];
    const float* Va   = (const float*)d_in[8];
    const float* bva  = (const float*)d_in[9];
    const float* Wih  = (const float*)d_in[10];
    const float* Whh  = (const float*)d_in[11];
    const float* bih  = (const float*)d_in[12];
    const float* bhh  = (const float*)d_in[13];
    const float* W1   = (const float*)d_in[14];
    const float* b1   = (const float*)d_in[15];
    const float* W2   = (const float*)d_in[16];
    const float* b2   = (const float*)d_in[17];
    const float* W3   = (const float*)d_in[18];
    const float* b3   = (const float*)d_in[19];
    float* out = (float*)d_out;

    cudaFuncSetAttribute(k_scores, cudaFuncAttributeMaxDynamicSharedMemorySize, SMEM_SCORES);

    k_prep<<<4, 256>>>(Ua);
    k_qproj<<<B, 256>>>(h0, Wa, ba, bua, Whh, bhh);
    dim3 g2(T / MTILE, B);
    k_scores<<<g2, 512, SMEM_SCORES>>>(enc, Ua, Va, bva);
    k_softmax_ctx<<<B, 1024>>>(enc);
    dim3 g4(4, B);
    k_base<<<g4, 256>>>(Wih, bih);
    k_steps<<<B, 256>>>(x, c0, W1, b1, W2, b2, W3, b3, out);
}

// round 12
// speedup vs baseline: 1.8872x; 1.0200x over previous
#include <cuda_runtime.h>
#include <cuda_bf16.h>
#include <cstdint>
#include <cstddef>

#define B 128
#define T 2048
#define H 200
#define H4 800

// ---------------- device scratch ----------------
__device__ float g_qp[B * H];
__device__ float g_hpre[B * H4];
__device__ float g_scores[B * T];       // scores, then exp(s-max) in-place
__device__ float g_inv[B];              // 1/softmax_total
__device__ float g_ctxp[8 * B * H];     // context partials
__device__ float g_base[B * H4];
__device__ float g_wx0[H4];
// Pre-packed Ua fragments: [chunk][kk][q][n(stride 218)] -> uint4(b0h,b1h,b0l,b1l)
__device__ uint4 g_Bpk[4 * 4 * 4 * 218 / 1];   // 13952 uint4

__device__ __forceinline__ float tanh_fast(float x) {
    float p = __expf(2.0f * x);
    return 1.0f - __fdividef(2.0f, p + 1.0f);
}
__device__ __forceinline__ float sig_fast(float x) {
    return __fdividef(1.0f, 1.0f + __expf(-x));
}
__device__ __forceinline__ uint32_t pack_bf2(__nv_bfloat16 a, __nv_bfloat16 b) {
    return (uint32_t)__bfloat16_as_ushort(a) | ((uint32_t)__bfloat16_as_ushort(b) << 16);
}
__device__ __forceinline__ void split_bf(float v, __nv_bfloat16& h, __nv_bfloat16& l) {
    h = __float2bfloat16(v);
    l = __float2bfloat16(v - __bfloat162float(h));
}
__device__ __forceinline__ void mma_bf16(float* c, const uint32_t* a, uint32_t b0, uint32_t b1) {
    asm volatile(
        "mma.sync.aligned.m16n8k16.row.col.f32.bf16.bf16.f32 "
        "{%0,%1,%2,%3}, {%4,%5,%6,%7}, {%8,%9}, {%0,%1,%2,%3};"
        : "+f"(c[0]), "+f"(c[1]), "+f"(c[2]), "+f"(c[3])
        : "r"(a[0]), "r"(a[1]), "r"(a[2]), "r"(a[3]), "r"(b0), "r"(b1));
}

#define NB 218           // padded n-stride for B fragments (bank-conflict-free)
#define B_CHUNK_U4 3488  // 4kk * 4q * 218 uint4 per chunk

// ---------------------------------------------------------------------------
// K0: pre-pack Ua into fragment-order uint4 (b0h, b1h, b0l, b1l). grid(4), 256.
// pair p0 = chunk*32 + kk*8 + q -> b0 = k{2p0, 2p0+1}; b1 = pair p0+4.
// ---------------------------------------------------------------------------
__global__ __launch_bounds__(256) void k_prep(const float* __restrict__ Ua)
{
    int chunk = blockIdx.x, tid = threadIdx.x;
    for (int e = tid; e < 4 * 4 * 216; e += 256) {
        int kk = e / (4 * 216);
        int r = e % (4 * 216);
        int q = r / 216, n = r % 216;
        int p0 = chunk * 32 + kk * 8 + q;
        int k0 = 2 * p0;          // b0 k-indices k0, k0+1
        int k1 = k0 + 8;          // b1 k-indices k1, k1+1
        float a0 = 0.f, a1 = 0.f, a2 = 0.f, a3 = 0.f;
        if (n < H) {
            if (k0 < H)     a0 = Ua[(size_t)n * H + k0];
            if (k0 + 1 < H) a1 = Ua[(size_t)n * H + k0 + 1];
            if (k1 < H)     a2 = Ua[(size_t)n * H + k1];
            if (k1 + 1 < H) a3 = Ua[(size_t)n * H + k1 + 1];
        }
        __nv_bfloat16 h0, l0, h1, l1, h2, l2, h3, l3;
        split_bf(a0, h0, l0); split_bf(a1, h1, l1);
        split_bf(a2, h2, l2); split_bf(a3, h3, l3);
        uint4 v;
        v.x = pack_bf2(h0, h1);   // b0h
        v.y = pack_bf2(h2, h3);   // b1h
        v.z = pack_bf2(l0, l1);   // b0l
        v.w = pack_bf2(l2, l3);   // b1l
        g_Bpk[((size_t)(chunk * 4 + kk) * 4 + q) * NB + n] = v;
    }
    // zero the n=216,217 padding
    if (tid < 32) {
        int kk = tid >> 3, q = (tid >> 1) & 3, n = 216 + (tid & 1);
        g_Bpk[((size_t)(chunk * 4 + kk) * 4 + q) * NB + n] = make_uint4(0, 0, 0, 0);
    }
}

// ---------------------------------------------------------------------------
// K1: q_proj + h_pre
// ---------------------------------------------------------------------------
__global__ __launch_bounds__(256) void k_qproj(
    const float* __restrict__ h0, const float* __restrict__ Wa,
    const float* __restrict__ ba, const float* __restrict__ bua,
    const float* __restrict__ Whh, const float* __restrict__ bhh)
{
    int b = blockIdx.x, tid = threadIdx.x;
    __shared__ float qs[H];
    if (tid < H) qs[tid] = h0[b * H + tid];
    __syncthreads();

    if (tid < H) {
        const float* w = Wa + tid * H;
        float a0 = 0.f, a1 = 0.f, a2 = 0.f, a3 = 0.f;
        #pragma unroll 4
        for (int k = 0; k < H; k += 4) {
            a0 += w[k] * qs[k];     a1 += w[k+1] * qs[k+1];
            a2 += w[k+2] * qs[k+2]; a3 += w[k+3] * qs[k+3];
        }
        g_qp[b * H + tid] = a0 + a1 + a2 + a3 + ba[tid] + bua[tid];
    }
    for (int j = tid; j < H4; j += 256) {
        const float* w = Whh + j * H;
        float a0 = 0.f, a1 = 0.f, a2 = 0.f, a3 = 0.f;
        #pragma unroll 4
        for (int k = 0; k < H; k += 4) {
            a0 += w[k] * qs[k];     a1 += w[k+1] * qs[k+1];
            a2 += w[k+2] * qs[k+2]; a3 += w[k+3] * qs[k+3];
        }
        g_hpre[b * H4 + j] = a0 + a1 + a2 + a3 + bhh[j];
    }
}

// ---------------------------------------------------------------------------
// K2: scores via mma.sync, fragment-packed smem (LDS.128 everywhere).
// Tile M=128 x N=208, K=208 padded; K chunks of 64.
// A smem: [mf 0..7][kk 0..3][lane 0..31][reg 0..3] u32, kk-stride 132 u32.
// grid(16, 128), 512 threads (16 warps: widM=wid>>1 m-band, widN=wid&1 n-half).
// ---------------------------------------------------------------------------
#define MTILE 128
#define NTILE 208
#define A_KK_STRIDE 132                // 32 lanes * 4 regs + 4 pad (u32)
#define A_SIZE_U32 (8 * 4 * A_KK_STRIDE)   // 4224 u32 = 16896 B
// smem byte offsets
#define OFF_QPS  0
#define OFF_VAS  832
#define OFF_SRED 1664
#define OFF_AH   2688
#define OFF_AL   (OFF_AH + A_SIZE_U32 * 4)          // 19584
#define OFF_B    (OFF_AL + A_SIZE_U32 * 4)          // 36480
#define SMEM_SCORES (OFF_B + B_CHUNK_U4 * 16)       // 92288

__global__ __launch_bounds__(512) void k_scores(
    const float* __restrict__ enc,
    const float* __restrict__ Va, const float* __restrict__ bva)
{
    extern __shared__ char smem[];
    const int tid = threadIdx.x;
    const int wid = tid >> 5, lane = tid & 31;
    const int mf = wid >> 1, widN = wid & 1;
    const int b = blockIdx.y;
    const int t0 = blockIdx.x * MTILE;

    float* qps = (float*)(smem + OFF_QPS);
    float* Vas = (float*)(smem + OFF_VAS);
    float* sred = (float*)(smem + OFF_SRED);
    uint32_t* Ah32 = (uint32_t*)(smem + OFF_AH);
    uint32_t* Al32 = (uint32_t*)(smem + OFF_AL);
    uint4* Bf = (uint4*)(smem + OFF_B);

    if (tid < NTILE) {
        Vas[tid] = (tid < H) ? Va[tid] : 0.f;
        qps[tid] = (tid < H) ? g_qp[b * H + tid] : 0.f;
    }

    float acc[13][4];
    #pragma unroll
    for (int j = 0; j < 13; ++j)
        #pragma unroll
        for (int i = 0; i < 4; ++i) acc[j][i] = 0.f;

    const float* encb = enc + ((size_t)b * T + t0) * H;
    const int q = lane & 3, nn = lane >> 2;

    for (int c = 0; c < 4; ++c) {
        const int k0 = c * 64;
        const int nsteps = (c < 3) ? 4 : 1;
        // ---- produce A fragments (fp32 -> bf16 hi/lo, fragment order) ----
        #pragma unroll
        for (int it = 0; it < 4; ++it) {
            int idx = it * 512 + tid;
            int r = idx >> 4, c4 = idx & 15;
            int kg = k0 + c4 * 4;
            float4 v = make_float4(0.f, 0.f, 0.f, 0.f);
            if (kg < H) v = *(const float4*)(encb + (size_t)r * H + kg);
            __nv_bfloat16 hx, lx, hy, ly, hz, lz, hw, lw;
            split_bf(v.x, hx, lx); split_bf(v.y, hy, ly);
            split_bf(v.z, hz, lz); split_bf(v.w, hw, lw);
            int mfw = r >> 4, ri = r & 15;
            int kkw = c4 >> 2;
            int pl = (c4 & 3) * 2;                       // p_local in {0,2,4,6}
            int r0 = (ri >> 3) + ((pl & 4) ? 2 : 0);
            int L = (ri & 7) * 4 + (pl & 3);
            int base = (mfw * 4 + kkw) * A_KK_STRIDE + r0;
            Ah32[base + L * 4]       = pack_bf2(hx, hy);
            Ah32[base + (L + 1) * 4] = pack_bf2(hz, hw);
            Al32[base + L * 4]       = pack_bf2(lx, ly);
            Al32[base + (L + 1) * 4] = pack_bf2(lz, lw);
        }
        // ---- copy pre-packed B fragments for this chunk ----
        {
            const uint4* src = g_Bpk + (size_t)c * B_CHUNK_U4;
            const int cnt = nsteps * 872;                // 4q * 218 per kk
            for (int i = tid; i < cnt; i += 512) Bf[i] = src[i];
        }
        __syncthreads();

        for (int kk = 0; kk < nsteps; ++kk) {
            const uint4 ah4 = *(const uint4*)(Ah32 + (mf * 4 + kk) * A_KK_STRIDE + lane * 4);
            const uint4 al4 = *(const uint4*)(Al32 + (mf * 4 + kk) * A_KK_STRIDE + lane * 4);
            uint32_t ah[4] = {ah4.x, ah4.y, ah4.z, ah4.w};
            uint32_t al[4] = {al4.x, al4.y, al4.z, al4.w};
            const uint4* brow = Bf + (kk * 4 + q) * NB + widN * 104 + nn;
            #pragma unroll
            for (int j = 0; j < 13; ++j) {
                uint4 bf = brow[j * 8];
                mma_bf16(acc[j], ah, bf.x, bf.y);
                mma_bf16(acc[j], al, bf.x, bf.y);
                mma_bf16(acc[j], ah, bf.z, bf.w);
            }
        }
        __syncthreads();
    }

    // ---- epilogue: tanh + Va weighted sum, quad shuffle-reduce ----
    float p0 = 0.f, p1 = 0.f;
    #pragma unroll
    for (int j = 0; j < 13; ++j) {
        int n0 = widN * 104 + j * 8 + q * 2;
        float va0 = Vas[n0], va1 = Vas[n0 + 1];
        float q0 = qps[n0], q1 = qps[n0 + 1];
        p0 += va0 * tanh_fast(q0 + acc[j][0]) + va1 * tanh_fast(q1 + acc[j][1]);
        p1 += va0 * tanh_fast(q0 + acc[j][2]) + va1 * tanh_fast(q1 + acc[j][3]);
    }
    p0 += __shfl_xor_sync(0xffffffffu, p0, 1);
    p0 += __shfl_xor_sync(0xffffffffu, p0, 2);
    p1 += __shfl_xor_sync(0xffffffffu, p1, 1);
    p1 += __shfl_xor_sync(0xffffffffu, p1, 2);
    if (q == 0) {
        int r0 = mf * 16 + nn;
        sred[r0 * 2 + widN] = p0;
        sred[(r0 + 8) * 2 + widN] = p1;
    }
    __syncthreads();
    if (tid < MTILE)
        g_scores[(size_t)b * T + t0 + tid] = bva[0] + sred[tid * 2] + sred[tid * 2 + 1];
}

// ---------------------------------------------------------------------------
// K3a: softmax over scores only (in-place exp + 1/total). grid(B), 256.
// ---------------------------------------------------------------------------
__global__ __launch_bounds__(256) void k_softmax()
{
    int b = blockIdx.x, tid = threadIdx.x;
    __shared__ float red[256];
    float* sb = g_scores + (size_t)b * T;

    float m = -1e30f;
    float v[8];
    #pragma unroll
    for (int i = 0; i < 8; ++i) {
        v[i] = sb[tid + i * 256];
        m = fmaxf(m, v[i]);
    }
    red[tid] = m;
    __syncthreads();
    for (int s = 128; s > 0; s >>= 1) {
        if (tid < s) red[tid] = fmaxf(red[tid], red[tid + s]);
        __syncthreads();
    }
    float mx = red[0];
    __syncthreads();

    float sum = 0.f;
    #pragma unroll
    for (int i = 0; i < 8; ++i) {
        float e = __expf(v[i] - mx);
        sb[tid + i * 256] = e;
        sum += e;
    }
    red[tid] = sum;
    __syncthreads();
    for (int s = 128; s > 0; s >>= 1) {
        if (tid < s) red[tid] += red[tid + s];
        __syncthreads();
    }
    if (tid == 0) g_inv[b] = 1.0f / red[0];
}

// ---------------------------------------------------------------------------
// K3b: context partials: part[g][b][h] = sum_{t in g-th 256} w[t]*enc[b,t,h]
// grid(8, B), 256 threads. Pure streaming, no block reductions.
// ---------------------------------------------------------------------------
__global__ __launch_bounds__(256) void k_ctx(const float* __restrict__ enc)
{
    int g = blockIdx.x, b = blockIdx.y, tid = threadIdx.x;
    __shared__ float w[256];
    w[tid] = g_scores[(size_t)b * T + g * 256 + tid];
    __syncthreads();
    if (tid < H) {
        const float* e = enc + ((size_t)b * T + g * 256) * H + tid;
        float a0 = 0.f, a1 = 0.f, a2 = 0.f, a3 = 0.f;
        #pragma unroll 4
        for (int t = 0; t < 256; t += 4) {
            a0 += w[t]     * e[(size_t)t * H];
            a1 += w[t + 1] * e[(size_t)(t + 1) * H];
            a2 += w[t + 2] * e[(size_t)(t + 2) * H];
            a3 += w[t + 3] * e[(size_t)(t + 3) * H];
        }
        g_ctxp[((size_t)g * B + b) * H + tid] = a0 + a1 + a2 + a3;
    }
}

// ---------------------------------------------------------------------------
// K4a: base gates (sums the 8 ctx partials). grid(4, B), 256 threads.
// ---------------------------------------------------------------------------
__global__ __launch_bounds__(256) void k_base(
    const float* __restrict__ Wih, const float* __restrict__ bih)
{
    int b = blockIdx.y, tid = threadIdx.x;
    __shared__ float ctx[H];
    if (tid < H) {
        float s = 0.f;
        #pragma unroll
        for (int g = 0; g < 8; ++g) s += g_ctxp[((size_t)g * B + b) * H + tid];
        ctx[tid] = s * g_inv[b];
    }
    __syncthreads();
    if (tid < H) {
        int j = blockIdx.x * H + tid;
        const float* w = Wih + (size_t)j * 201;
        const float* wc = w + 1;
        float a0 = 0.f, a1 = 0.f, a2 = 0.f, a3 = 0.f;
        #pragma unroll 4
        for (int k = 0; k < H; k += 4) {
            a0 += wc[k] * ctx[k];     a1 += wc[k+1] * ctx[k+1];
            a2 += wc[k+2] * ctx[k+2]; a3 += wc[k+3] * ctx[k+3];
        }
        g_base[b * H4 + j] = a0 + a1 + a2 + a3 + bih[j] + g_hpre[b * H4 + j];
        if (b == 0) g_wx0[j] = w[0];
    }
}

// ---------------------------------------------------------------------------
// K4b: 5-step scalar-feedback decoder. grid(B), 256 threads.
// ---------------------------------------------------------------------------
__global__ __launch_bounds__(256) void k_steps(
    const float* __restrict__ x_in, const float* __restrict__ c0,
    const float* __restrict__ W1, const float* __restrict__ b1,
    const float* __restrict__ W2, const float* __restrict__ b2,
    const float* __restrict__ W3, const float* __restrict__ b3,
    float* __restrict__ out)
{
    int b = blockIdx.x, tid = threadIdx.x;
    __shared__ float bs[H4], ws[H4], c0s[H], hbuf[H], o1[100], o2[50];
    __shared__ float xs;

    for (int i = tid; i < H4; i += 256) {
        bs[i] = g_base[b * H4 + i];
        ws[i] = g_wx0[i];
    }
    if (tid < H) c0s[tid] = c0[b * H + tid];
    if (tid == 0) xs = x_in[b];
    __syncthreads();

    for (int s = 0; s < 5; ++s) {
        float xv = xs;
        if (tid < H) {
            float ig = bs[tid]       + ws[tid]       * xv;
            float fg = bs[200 + tid] + ws[200 + tid] * xv;
            float gg = bs[400 + tid] + ws[400 + tid] * xv;
            float og = bs[600 + tid] + ws[600 + tid] * xv;
            float cn = sig_fast(fg) * c0s[tid] + sig_fast(ig) * tanh_fast(gg);
            float hn = sig_fast(og) * tanh_fast(cn);
            hbuf[tid] = fmaxf(hn, 0.f);
        }
        __syncthreads();
        if (tid < 100) {
            const float* w = W1 + tid * H;
            float a0 = 0.f, a1 = 0.f, a2 = 0.f, a3 = 0.f;
            #pragma unroll 4
            for (int k = 0; k < H; k += 4) {
                a0 += w[k] * hbuf[k];     a1 += w[k+1] * hbuf[k+1];
                a2 += w[k+2] * hbuf[k+2]; a3 += w[k+3] * hbuf[k+3];
            }
            o1[tid] = fmaxf(a0 + a1 + a2 + a3 + b1[tid], 0.f);
        }
        __syncthreads();
        if (tid < 50) {
            const float* w = W2 + tid * 100;
            float a0 = 0.f, a1 = 0.f, a2 = 0.f, a3 = 0.f;
            #pragma unroll 4
            for (int k = 0; k < 100; k += 4) {
                a0 += w[k] * o1[k];     a1 += w[k+1] * o1[k+1];
                a2 += w[k+2] * o1[k+2]; a3 += w[k+3] * o1[k+3];
            }
            o2[tid] = fmaxf(a0 + a1 + a2 + a3 + b2[tid], 0.f);
        }
        __syncthreads();
        if (tid < 32) {
            float a = (tid < 50) ? W3[tid] * o2[tid] : 0.f;
            if (tid + 32 < 50) a += W3[tid + 32] * o2[tid + 32];
            #pragma unroll
            for (int sh = 16; sh > 0; sh >>= 1)
                a += __shfl_down_sync(0xffffffffu, a, sh);
            if (tid == 0) {
                float y = a + b3[0];
                out[b * 5 + s] = y;
                xs = y;
            }
        }
        __syncthreads();
    }
}

// ---------------------------------------------------------------------------
extern "C" void kernel_launch(void* const* d_in, const int* in_sizes, int n_in,
                              void* d_out, int out_size)
{
    const float* x    = (const float*)d_in[0];
    const float* h0   = (const float*)d_in[1];
    const float* c0   = (const float*)d_in[2];
    const float* enc  = (const float*)d_in[3];
    const float* Wa   = (const float*)d_in[4];
    const float* ba   = (const float*)d_in[5];
    const float* Ua   = (const float*)d_in[6];
    const float* bua  = (const float*)d_in[7];
    const float* Va   = (const float*)d_in[8];
    const float* bva  = (const float*)d_in[9];
    const float* Wih  = (const float*)d_in[10];
    const float* Whh  = (const float*)d_in[11];
    const float* bih  = (const float*)d_in[12];
    const float* bhh  = (const float*)d_in[13];
    const float* W1   = (const float*)d_in[14];
    const float* b1   = (const float*)d_in[15];
    const float* W2   = (const float*)d_in[16];
    const float* b2   = (const float*)d_in[17];
    const float* W3   = (const float*)d_in[18];
    const float* b3   = (const float*)d_in[19];
    float* out = (float*)d_out;

    cudaFuncSetAttribute(k_scores, cudaFuncAttributeMaxDynamicSharedMemorySize, SMEM_SCORES);

    k_prep<<<4, 256>>>(Ua);
    k_qproj<<<B, 256>>>(h0, Wa, ba, bua, Whh, bhh);
    dim3 g2(T / MTILE, B);
    k_scores<<<g2, 512, SMEM_SCORES>>>(enc, Va, bva);
    k_softmax<<<B, 256>>>();
    dim3 g3(8, B);
    k_ctx<<<g3, 256>>>(enc);
    dim3 g4(4, B);
    k_base<<<g4, 256>>>(Wih, bih);
    k_steps<<<B, 256>>>(x, c0, W1, b1, W2, b2, W3, b3, out);
}

// round 14
// speedup vs baseline: 1.9509x; 1.0337x over previous
#include <cuda_runtime.h>
#include <cuda_fp16.h>
#include <cstdint>
#include <cstddef>

#define B 128
#define T 2048
#define H 200
#define H4 800

// ---------------- device scratch ----------------
__device__ float g_qp[B * H];
__device__ float g_hpre[B * H4];
__device__ float g_scores[B * T];       // scores, then exp(s-max) in-place
__device__ float g_inv[B];              // 1/softmax_total
__device__ float g_ctxp[8 * B * H];     // context partials
__device__ float g_base[B * H4];
__device__ float g_wx0[H4];
// Pre-packed Ua fragments fp16 hi/lo: [chunk][kk][q][n(stride 232)] -> uint4(b0h,b1h,b0l,b1l)
#define NB4 232
#define B_CHUNK_U4 (16 * NB4)           // 3712 uint4 per chunk
__device__ uint4 g_Bpk[4 * B_CHUNK_U4];

__device__ __forceinline__ float tanh_fast(float x) {
    float p = __expf(2.0f * x);
    return 1.0f - __fdividef(2.0f, p + 1.0f);
}
__device__ __forceinline__ float sig_fast(float x) {
    return __fdividef(1.0f, 1.0f + __expf(-x));
}
__device__ __forceinline__ uint32_t pack_h2(__half a, __half b) {   // low=a, high=b
    return (uint32_t)__half_as_ushort(a) | ((uint32_t)__half_as_ushort(b) << 16);
}
__device__ __forceinline__ void mma_f16(float* c, const uint32_t* a, uint32_t b0, uint32_t b1) {
    asm volatile(
        "mma.sync.aligned.m16n8k16.row.col.f32.f16.f16.f32 "
        "{%0,%1,%2,%3}, {%4,%5,%6,%7}, {%8,%9}, {%0,%1,%2,%3};"
        : "+f"(c[0]), "+f"(c[1]), "+f"(c[2]), "+f"(c[3])
        : "r"(a[0]), "r"(a[1]), "r"(a[2]), "r"(a[3]), "r"(b0), "r"(b1));
}
__device__ __forceinline__ uint32_t smem_u32(const void* p) {
    uint32_t a;
    asm("{ .reg .u64 t; cvta.to.shared.u64 t, %1; cvt.u32.u64 %0, t; }" : "=r"(a) : "l"(p));
    return a;
}
#define CP_ASYNC16(dst, src, sz) \
    asm volatile("cp.async.cg.shared.global [%0], [%1], 16, %2;" \
                 :: "r"(dst), "l"(src), "r"(sz) : "memory")
#define CP_COMMIT() asm volatile("cp.async.commit_group;" ::: "memory")
#define CP_WAIT0()  asm volatile("cp.async.wait_group 0;" ::: "memory")

// ---------------------------------------------------------------------------
// K0: pre-pack Ua into fp16 hi/lo fragment order. grid(4), 256 threads.
// b0 = k{2p0, 2p0+1}, b1 = k{2p0+8, 2p0+9}, p0 = chunk*32 + kk*8 + q.
// ---------------------------------------------------------------------------
__global__ __launch_bounds__(256) void k_prep(const float* __restrict__ Ua)
{
    int chunk = blockIdx.x, tid = threadIdx.x;
    for (int e = tid; e < 16 * NB4; e += 256) {
        int kk = e / (4 * NB4);
        int r = e % (4 * NB4);
        int q = r / NB4, n = r % NB4;
        int p0 = chunk * 32 + kk * 8 + q;
        int k0 = 2 * p0, k1 = k0 + 8;
        float a0 = 0.f, a1 = 0.f, a2 = 0.f, a3 = 0.f;
        if (n < H) {
            if (k0 < H)     a0 = Ua[(size_t)n * H + k0];
            if (k0 + 1 < H) a1 = Ua[(size_t)n * H + k0 + 1];
            if (k1 < H)     a2 = Ua[(size_t)n * H + k1];
            if (k1 + 1 < H) a3 = Ua[(size_t)n * H + k1 + 1];
        }
        __half h0 = __float2half_rn(a0), h1 = __float2half_rn(a1);
        __half h2 = __float2half_rn(a2), h3 = __float2half_rn(a3);
        __half l0 = __float2half_rn(a0 - __half2float(h0));
        __half l1 = __float2half_rn(a1 - __half2float(h1));
        __half l2 = __float2half_rn(a2 - __half2float(h2));
        __half l3 = __float2half_rn(a3 - __half2float(h3));
        uint4 v;
        v.x = pack_h2(h0, h1);
        v.y = pack_h2(h2, h3);
        v.z = pack_h2(l0, l1);
        v.w = pack_h2(l2, l3);
        g_Bpk[(size_t)chunk * B_CHUNK_U4 + (kk * 4 + q) * NB4 + n] = v;
    }
}

// ---------------------------------------------------------------------------
// K1a: q_proj
// ---------------------------------------------------------------------------
__global__ __launch_bounds__(256) void k_qp(
    const float* __restrict__ h0, const float* __restrict__ Wa,
    const float* __restrict__ ba, const float* __restrict__ bua)
{
    int b = blockIdx.x, tid = threadIdx.x;
    __shared__ float qs[H];
    if (tid < H) qs[tid] = h0[b * H + tid];
    __syncthreads();
    if (tid < H) {
        const float* w = Wa + tid * H;
        float a0 = 0.f, a1 = 0.f, a2 = 0.f, a3 = 0.f;
        #pragma unroll 4
        for (int k = 0; k < H; k += 4) {
            a0 += w[k] * qs[k];     a1 += w[k+1] * qs[k+1];
            a2 += w[k+2] * qs[k+2]; a3 += w[k+3] * qs[k+3];
        }
        g_qp[b * H + tid] = a0 + a1 + a2 + a3 + ba[tid] + bua[tid];
    }
}

// ---------------------------------------------------------------------------
// K1b: h_pre
// ---------------------------------------------------------------------------
__global__ __launch_bounds__(256) void k_hpre(
    const float* __restrict__ h0, const float* __restrict__ Whh,
    const float* __restrict__ bhh)
{
    int b = blockIdx.x, tid = threadIdx.x;
    __shared__ float qs[H];
    if (tid < H) qs[tid] = h0[b * H + tid];
    __syncthreads();
    for (int j = tid; j < H4; j += 256) {
        const float* w = Whh + j * H;
        float a0 = 0.f, a1 = 0.f, a2 = 0.f, a3 = 0.f;
        #pragma unroll 4
        for (int k = 0; k < H; k += 4) {
            a0 += w[k] * qs[k];     a1 += w[k+1] * qs[k+1];
            a2 += w[k+2] * qs[k+2]; a3 += w[k+3] * qs[k+3];
        }
        g_hpre[b * H4 + j] = a0 + a1 + a2 + a3 + bhh[j];
    }
}

// ---------------------------------------------------------------------------
// K2: scores via mma.sync fp16 2-pass (A single fp16, B hi+lo).
// Tile M=128 x N=224(pad of 208), K chunks of 64; cp.async double-buffered.
// 512 threads = 16 warps: band = wid>>2 (32 rows), widN = wid&3 (56 cols).
// grid(16, 128)
// ---------------------------------------------------------------------------
#define MTILE 128
#define NPAD 224
#define A_KK_STRIDE 132                     // u32: 32 lanes * 4 + 4 pad
#define A_SIZE_U32 (8 * 4 * A_KK_STRIDE)    // 4224 u32 = 16896 B
// smem byte offsets
#define OFF_QPS   0                          // 224 f = 896
#define OFF_VAS   896                        // 896
#define OFF_SRED  1792                       // 128*4 f = 2048
#define OFF_AF    3840                       // 16896
#define OFF_ARAW  20736                      // 2 x 32768
#define OFF_B     86272                      // 2 x 59392
#define SMEM_SCORES 205056

__global__ __launch_bounds__(512) void k_scores(
    const float* __restrict__ enc,
    const float* __restrict__ Va, const float* __restrict__ bva)
{
    extern __shared__ char smem[];
    const uint32_t sb = smem_u32(smem);
    const int tid = threadIdx.x;
    const int wid = tid >> 5, lane = tid & 31;
    const int band = wid >> 2, widN = wid & 3;
    const int b = blockIdx.y;
    const int t0 = blockIdx.x * MTILE;

    float* qps = (float*)(smem + OFF_QPS);
    float* Vas = (float*)(smem + OFF_VAS);
    float* sred = (float*)(smem + OFF_SRED);          // [128][4]
    uint32_t* Af = (uint32_t*)(smem + OFF_AF);

    if (tid < NPAD) {
        Vas[tid] = (tid < H) ? Va[tid] : 0.f;
        qps[tid] = (tid < H) ? g_qp[b * H + tid] : 0.f;
    }

    float acc0[7][4], acc1[7][4];
    #pragma unroll
    for (int j = 0; j < 7; ++j)
        #pragma unroll
        for (int i = 0; i < 4; ++i) { acc0[j][i] = 0.f; acc1[j][i] = 0.f; }

    const float* encb = enc + ((size_t)b * T + t0) * H;
    const int q = lane & 3, nn = lane >> 2;

    // async loaders -------------------------------------------------------
    auto load_chunk = [&](int c, int buf) {
        // raw A: 2048 float4 (zero-fill beyond H via src-size)
        uint32_t adst = sb + OFF_ARAW + buf * 32768;
        #pragma unroll
        for (int it = 0; it < 4; ++it) {
            int idx = it * 512 + tid;
            int r = idx >> 4, c4 = idx & 15;
            int kg = c * 64 + c4 * 4;
            uint32_t sz = (kg + 4 <= H) ? 16u : 0u;
            const float* src = encb + (size_t)r * H + (sz ? kg : 0);
            CP_ASYNC16(adst + idx * 16, src, sz);
        }
        // packed B
        int cnt = ((c < 3) ? 4 : 1) * 4 * NB4;
        uint32_t bdst = sb + OFF_B + buf * 59392;
        const uint4* src = g_Bpk + (size_t)c * B_CHUNK_U4;
        for (int i = tid; i < cnt; i += 512)
            CP_ASYNC16(bdst + i * 16, src + i, 16u);
    };

    load_chunk(0, 0);
    CP_COMMIT();

    for (int c = 0; c < 4; ++c) {
        const int buf = c & 1;
        const int nsteps = (c < 3) ? 4 : 1;
        CP_WAIT0();
        __syncthreads();                       // chunk c resident; prev MMA done
        if (c < 3) { load_chunk(c + 1, buf ^ 1); CP_COMMIT(); }

        // convert raw A (fp32) -> fp16 fragments
        const float4* araw = (const float4*)(smem + OFF_ARAW + buf * 32768);
        #pragma unroll
        for (int it = 0; it < 4; ++it) {
            int idx = it * 512 + tid;
            float4 v = araw[idx];
            int r = idx >> 4, c4 = idx & 15;
            int kkw = c4 >> 2;
            int pl = (c4 & 3) * 2;
            int mfw = r >> 4, ri = r & 15;
            int r0 = (ri >> 3) + ((pl & 4) ? 2 : 0);
            int L = (ri & 7) * 4 + (pl & 3);
            int base = (mfw * 4 + kkw) * A_KK_STRIDE + r0;
            Af[base + L * 4]       = pack_h2(__float2half_rn(v.x), __float2half_rn(v.y));
            Af[base + (L + 1) * 4] = pack_h2(__float2half_rn(v.z), __float2half_rn(v.w));
        }
        __syncthreads();                       // fragments ready

        const uint4* Bf = (const uint4*)(smem + OFF_B + buf * 59392);
        for (int kk = 0; kk < nsteps; ++kk) {
            const uint4 a0v = *(const uint4*)(Af + ((band * 2) * 4 + kk) * A_KK_STRIDE + lane * 4);
            const uint4 a1v = *(const uint4*)(Af + ((band * 2 + 1) * 4 + kk) * A_KK_STRIDE + lane * 4);
            uint32_t a0[4] = {a0v.x, a0v.y, a0v.z, a0v.w};
            uint32_t a1[4] = {a1v.x, a1v.y, a1v.z, a1v.w};
            const uint4* brow = Bf + (kk * 4 + q) * NB4 + widN * 56 + nn;
            #pragma unroll
            for (int j = 0; j < 7; ++j) {
                uint4 bf = brow[j * 8];
                mma_f16(acc0[j], a0, bf.x, bf.y);
                mma_f16(acc0[j], a0, bf.z, bf.w);
                mma_f16(acc1[j], a1, bf.x, bf.y);
                mma_f16(acc1[j], a1, bf.z, bf.w);
            }
        }
    }

    // ---- epilogue: tanh + Va weighted sum ----
    float p00 = 0.f, p01 = 0.f, p10 = 0.f, p11 = 0.f;
    #pragma unroll
    for (int j = 0; j < 7; ++j) {
        int n0 = widN * 56 + j * 8 + q * 2;
        float va0 = Vas[n0], va1 = Vas[n0 + 1];
        float q0 = qps[n0], q1 = qps[n0 + 1];
        p00 += va0 * tanh_fast(q0 + acc0[j][0]) + va1 * tanh_fast(q1 + acc0[j][1]);
        p01 += va0 * tanh_fast(q0 + acc0[j][2]) + va1 * tanh_fast(q1 + acc0[j][3]);
        p10 += va0 * tanh_fast(q0 + acc1[j][0]) + va1 * tanh_fast(q1 + acc1[j][1]);
        p11 += va0 * tanh_fast(q0 + acc1[j][2]) + va1 * tanh_fast(q1 + acc1[j][3]);
    }
    #pragma unroll
    for (int sh = 1; sh <= 2; sh <<= 1) {
        p00 += __shfl_xor_sync(0xffffffffu, p00, sh);
        p01 += __shfl_xor_sync(0xffffffffu, p01, sh);
        p10 += __shfl_xor_sync(0xffffffffu, p10, sh);
        p11 += __shfl_xor_sync(0xffffffffu, p11, sh);
    }
    if (q == 0) {
        int r0 = band * 32 + nn;
        sred[r0 * 4 + widN]        = p00;
        sred[(r0 + 8) * 4 + widN]  = p01;
        sred[(r0 + 16) * 4 + widN] = p10;
        sred[(r0 + 24) * 4 + widN] = p11;
    }
    __syncthreads();
    if (tid < MTILE) {
        float4 s4 = *(const float4*)(sred + tid * 4);
        g_scores[(size_t)b * T + t0 + tid] = bva[0] + s4.x + s4.y + s4.z + s4.w;
    }
}

// ---------------------------------------------------------------------------
// K3a: softmax over scores (in-place exp + 1/total). grid(B), 256.
// ---------------------------------------------------------------------------
__global__ __launch_bounds__(256) void k_softmax()
{
    int b = blockIdx.x, tid = threadIdx.x;
    __shared__ float red[256];
    float* sb = g_scores + (size_t)b * T;

    float m = -1e30f;
    float v[8];
    #pragma unroll
    for (int i = 0; i < 8; ++i) {
        v[i] = sb[tid + i * 256];
        m = fmaxf(m, v[i]);
    }
    red[tid] = m;
    __syncthreads();
    for (int s = 128; s > 0; s >>= 1) {
        if (tid < s) red[tid] = fmaxf(red[tid], red[tid + s]);
        __syncthreads();
    }
    float mx = red[0];
    __syncthreads();

    float sum = 0.f;
    #pragma unroll
    for (int i = 0; i < 8; ++i) {
        float e = __expf(v[i] - mx);
        sb[tid + i * 256] = e;
        sum += e;
    }
    red[tid] = sum;
    __syncthreads();
    for (int s = 128; s > 0; s >>= 1) {
        if (tid < s) red[tid] += red[tid + s];
        __syncthreads();
    }
    if (tid == 0) g_inv[b] = 1.0f / red[0];
}

// ---------------------------------------------------------------------------
// K3b: context partials, MLP=8. grid(8, B), 256 threads.
// ---------------------------------------------------------------------------
__global__ __launch_bounds__(256) void k_ctx(const float* __restrict__ enc)
{
    int g = blockIdx.x, b = blockIdx.y, tid = threadIdx.x;
    __shared__ float w[256];
    w[tid] = g_scores[(size_t)b * T + g * 256 + tid];
    __syncthreads();
    if (tid < H) {
        const float* e = enc + ((size_t)b * T + g * 256) * H + tid;
        float a0 = 0.f, a1 = 0.f, a2 = 0.f, a3 = 0.f;
        float a4 = 0.f, a5 = 0.f, a6 = 0.f, a7 = 0.f;
        #pragma unroll 4
        for (int t = 0; t < 256; t += 8) {
            a0 += w[t]     * e[(size_t)t * H];
            a1 += w[t + 1] * e[(size_t)(t + 1) * H];
            a2 += w[t + 2] * e[(size_t)(t + 2) * H];
            a3 += w[t + 3] * e[(size_t)(t + 3) * H];
            a4 += w[t + 4] * e[(size_t)(t + 4) * H];
            a5 += w[t + 5] * e[(size_t)(t + 5) * H];
            a6 += w[t + 6] * e[(size_t)(t + 6) * H];
            a7 += w[t + 7] * e[(size_t)(t + 7) * H];
        }
        g_ctxp[((size_t)g * B + b) * H + tid] =
            ((a0 + a1) + (a2 + a3)) + ((a4 + a5) + (a6 + a7));
    }
}

// ---------------------------------------------------------------------------
// K4a: base gates (sums 8 ctx partials). grid(4, B), 256 threads.
// ---------------------------------------------------------------------------
__global__ __launch_bounds__(256) void k_base(
    const float* __restrict__ Wih, const float* __restrict__ bih)
{
    int b = blockIdx.y, tid = threadIdx.x;
    __shared__ float ctx[H];
    if (tid < H) {
        float s = 0.f;
        #pragma unroll
        for (int g = 0; g < 8; ++g) s += g_ctxp[((size_t)g * B + b) * H + tid];
        ctx[tid] = s * g_inv[b];
    }
    __syncthreads();
    if (tid < H) {
        int j = blockIdx.x * H + tid;
        const float* w = Wih + (size_t)j * 201;
        const float* wc = w + 1;
        float a0 = 0.f, a1 = 0.f, a2 = 0.f, a3 = 0.f;
        #pragma unroll 4
        for (int k = 0; k < H; k += 4) {
            a0 += wc[k] * ctx[k];     a1 += wc[k+1] * ctx[k+1];
            a2 += wc[k+2] * ctx[k+2]; a3 += wc[k+3] * ctx[k+3];
        }
        g_base[b * H4 + j] = a0 + a1 + a2 + a3 + bih[j] + g_hpre[b * H4 + j];
        if (b == 0) g_wx0[j] = w[0];
    }
}

// ---------------------------------------------------------------------------
// K4b: 5-step scalar-feedback decoder. grid(B), 256 threads.
// ---------------------------------------------------------------------------
__global__ __launch_bounds__(256) void k_steps(
    const float* __restrict__ x_in, const float* __restrict__ c0,
    const float* __restrict__ W1, const float* __restrict__ b1,
    const float* __restrict__ W2, const float* __restrict__ b2,
    const float* __restrict__ W3, const float* __restrict__ b3,
    float* __restrict__ out)
{
    int b = blockIdx.x, tid = threadIdx.x;
    __shared__ float bs[H4], ws[H4], c0s[H], hbuf[H], o1[100], o2[50];
    __shared__ float xs;

    for (int i = tid; i < H4; i += 256) {
        bs[i] = g_base[b * H4 + i];
        ws[i] = g_wx0[i];
    }
    if (tid < H) c0s[tid] = c0[b * H + tid];
    if (tid == 0) xs = x_in[b];
    __syncthreads();

    for (int s = 0; s < 5; ++s) {
        float xv = xs;
        if (tid < H) {
            float ig = bs[tid]       + ws[tid]       * xv;
            float fg = bs[200 + tid] + ws[200 + tid] * xv;
            float gg = bs[400 + tid] + ws[400 + tid] * xv;
            float og = bs[600 + tid] + ws[600 + tid] * xv;
            float cn = sig_fast(fg) * c0s[tid] + sig_fast(ig) * tanh_fast(gg);
            float hn = sig_fast(og) * tanh_fast(cn);
            hbuf[tid] = fmaxf(hn, 0.f);
        }
        __syncthreads();
        if (tid < 100) {
            const float* w = W1 + tid * H;
            float a0 = 0.f, a1 = 0.f, a2 = 0.f, a3 = 0.f;
            #pragma unroll 4
            for (int k = 0; k < H; k += 4) {
                a0 += w[k] * hbuf[k];     a1 += w[k+1] * hbuf[k+1];
                a2 += w[k+2] * hbuf[k+2]; a3 += w[k+3] * hbuf[k+3];
            }
            o1[tid] = fmaxf(a0 + a1 + a2 + a3 + b1[tid], 0.f);
        }
        __syncthreads();
        if (tid < 50) {
            const float* w = W2 + tid * 100;
            float a0 = 0.f, a1 = 0.f, a2 = 0.f, a3 = 0.f;
            #pragma unroll 4
            for (int k = 0; k < 100; k += 4) {
                a0 += w[k] * o1[k];     a1 += w[k+1] * o1[k+1];
                a2 += w[k+2] * o1[k+2]; a3 += w[k+3] * o1[k+3];
            }
            o2[tid] = fmaxf(a0 + a1 + a2 + a3 + b2[tid], 0.f);
        }
        __syncthreads();
        if (tid < 32) {
            float a = (tid < 50) ? W3[tid] * o2[tid] : 0.f;
            if (tid + 32 < 50) a += W3[tid + 32] * o2[tid + 32];
            #pragma unroll
            for (int sh = 16; sh > 0; sh >>= 1)
                a += __shfl_down_sync(0xffffffffu, a, sh);
            if (tid == 0) {
                float y = a + b3[0];
                out[b * 5 + s] = y;
                xs = y;
            }
        }
        __syncthreads();
    }
}

// ---------------------------------------------------------------------------
extern "C" void kernel_launch(void* const* d_in, const int* in_sizes, int n_in,
                              void* d_out, int out_size)
{
    const float* x    = (const float*)d_in[0];
    const float* h0   = (const float*)d_in[1];
    const float* c0   = (const float*)d_in[2];
    const float* enc  = (const float*)d_in[3];
    const float* Wa   = (const float*)d_in[4];
    const float* ba   = (const float*)d_in[5];
    const float* Ua   = (const float*)d_in[6];
    const float* bua  = (const float*)d_in[7];
    const float* Va   = (const float*)d_in[8];
    const float* bva  = (const float*)d_in[9];
    const float* Wih  = (const float*)d_in[10];
    const float* Whh  = (const float*)d_in[11];
    const float* bih  = (const float*)d_in[12];
    const float* bhh  = (const float*)d_in[13];
    const float* W1   = (const float*)d_in[14];
    const float* b1   = (const float*)d_in[15];
    const float* W2   = (const float*)d_in[16];
    const float* b2   = (const float*)d_in[17];
    const float* W3   = (const float*)d_in[18];
    const float* b3   = (const float*)d_in[19];
    float* out = (float*)d_out;

    cudaFuncSetAttribute(k_scores, cudaFuncAttributeMaxDynamicSharedMemorySize, SMEM_SCORES);

    // launch index 3 = k_scores (profiled slot)
    k_prep<<<4, 256>>>(Ua);                               // 0
    k_qp<<<B, 256>>>(h0, Wa, ba, bua);                    // 1
    k_hpre<<<B, 256>>>(h0, Whh, bhh);                     // 2
    dim3 g2(T / MTILE, B);
    k_scores<<<g2, 512, SMEM_SCORES>>>(enc, Va, bva);     // 3
    k_softmax<<<B, 256>>>();                              // 4
    dim3 g3(8, B);
    k_ctx<<<g3, 256>>>(enc);                              // 5
    dim3 g4(4, B);
    k_base<<<g4, 256>>>(Wih, bih);                        // 6
    k_steps<<<B, 256>>>(x, c0, W1, b1, W2, b2, W3, b3, out); // 7
}